// round 15
// baseline (speedup 1.0000x reference)
#include <cuda_runtime.h>
#include <math.h>
#include <stdint.h>

#define NS_   8192
#define NK_   8192
#define HID_  1024
#define SENT_ 1024
#define TWOH_ 2048
#define RSPLIT 32

// ---------------- scratch (device globals; no allocations allowed) ----------
__device__ float g_S[(size_t)NS_ * HID_];        // S  [NS, HID]  fp32
__device__ float g_K[(size_t)NK_ * HID_];        // K  [NK, HID]  fp32
__device__ float g_Vt[(size_t)TWOH_ * NK_];      // V^T [2H, NK]  fp32
__device__ float g_pmax[RSPLIT * NK_];
__device__ float g_psum[RSPLIT * NK_];
__device__ float g_cmax[NK_];
__device__ float g_cinv[NK_];

// ---------------- helpers ----------------------------------------------------
__device__ __forceinline__ float tf32r(float x) {       // round-to-nearest tf32
    uint32_t r;
    asm("cvt.rna.tf32.f32 %0, %1;" : "=r"(r) : "f"(x));
    return __uint_as_float(r);
}

// m16n8k8 tf32 MMA (base PTX ISA — valid on compute_103 non-'a' target)
#define MMA8(cr, a, b)                                                        \
    asm volatile(                                                             \
        "mma.sync.aligned.m16n8k8.row.col.f32.tf32.tf32.f32 "                 \
        "{%0,%1,%2,%3},{%4,%5,%6,%7},{%8,%9},{%0,%1,%2,%3};"                  \
        : "+f"((cr)[0]), "+f"((cr)[1]), "+f"((cr)[2]), "+f"((cr)[3])          \
        : "r"((a)[0]), "r"((a)[1]), "r"((a)[2]), "r"((a)[3]),                 \
          "r"((b)[0]), "r"((b)[1]))

// ---------------- tensor-core GEMM  C = A * B^T (+bias) ---------------------
// A: [M,K] row-major fp32, B: [N,K] row-major fp32, C: [M,N] fp32.
// SPLIT: 3xTF32 (hi/lo split computed inline during tile load).
// Tile: BM=128, BN=128, BK=32; 256 threads = 8 warps (4 m x 2 n),
// warp tile 32x64 = 2 x 8 m16n8k8 fragments. Smem rows padded to 36 floats.
#define TROW 36
#define TILE_F (128 * TROW)                       // floats per tile buffer
#define SMEM_SPLIT  (4 * TILE_F * 4)              // 73728 B
#define SMEM_PLAIN  (2 * TILE_F * 4)              // 36864 B

template <bool SPLIT>
__device__ __forceinline__ void load_tile(const float* __restrict__ G,
                                          int row0, int Kd, int k0,
                                          float* __restrict__ sh,
                                          float* __restrict__ sl, int t)
{
    for (int idx = t; idx < 1024; idx += 256) {   // 128 rows x 8 float4
        int r  = idx >> 3;
        int c4 = (idx & 7) << 2;
        float4 v = *(const float4*)(G + (size_t)(row0 + r) * Kd + k0 + c4);
        float4 h;
        h.x = tf32r(v.x); h.y = tf32r(v.y); h.z = tf32r(v.z); h.w = tf32r(v.w);
        *(float4*)(sh + r * TROW + c4) = h;
        if (SPLIT) {
            float4 l;
            l.x = tf32r(v.x - h.x); l.y = tf32r(v.y - h.y);
            l.z = tf32r(v.z - h.z); l.w = tf32r(v.w - h.w);
            *(float4*)(sl + r * TROW + c4) = l;
        }
    }
}

template <bool SPLIT>
__global__ void __launch_bounds__(256, 1)
tgemm(const float* __restrict__ A, const float* __restrict__ B,
      const float* __restrict__ bias, float* __restrict__ C,
      int M, int N, int Kd)
{
    extern __shared__ float sm[];
    float* Ah = sm;
    float* Bh = sm + TILE_F;
    float* Al = sm + 2 * TILE_F;    // used only when SPLIT
    float* Bl = sm + 3 * TILE_F;

    const int t    = threadIdx.x;
    const int lane = t & 31;
    const int wid  = t >> 5;
    const int wm   = (wid & 3) * 32;     // warp m offset in tile
    const int wn   = (wid >> 2) * 64;    // warp n offset in tile
    const int row0 = blockIdx.y * 128;
    const int col0 = blockIdx.x * 128;
    const int ar   = lane >> 2;          // fragment row group
    const int ac   = lane & 3;           // fragment col group

    float c[2][8][4];
#pragma unroll
    for (int i = 0; i < 2; i++)
#pragma unroll
        for (int j = 0; j < 8; j++)
#pragma unroll
            for (int q = 0; q < 4; q++) c[i][j][q] = 0.0f;

    for (int k0 = 0; k0 < Kd; k0 += 32) {
        load_tile<SPLIT>(A, row0, Kd, k0, Ah, Al, t);
        load_tile<SPLIT>(B, col0, Kd, k0, Bh, Bl, t);
        __syncthreads();

#pragma unroll
        for (int kk = 0; kk < 4; kk++) {
            const int kb = kk * 8 + ac;
            uint32_t ah[2][4], bh[8][2];
            uint32_t al[2][4], bl[8][2];
#pragma unroll
            for (int i = 0; i < 2; i++) {
                const float* p = Ah + (wm + i * 16 + ar) * TROW + kb;
                ah[i][0] = __float_as_uint(p[0]);
                ah[i][1] = __float_as_uint(p[8 * TROW]);
                ah[i][2] = __float_as_uint(p[4]);
                ah[i][3] = __float_as_uint(p[8 * TROW + 4]);
                if (SPLIT) {
                    const float* q = Al + (wm + i * 16 + ar) * TROW + kb;
                    al[i][0] = __float_as_uint(q[0]);
                    al[i][1] = __float_as_uint(q[8 * TROW]);
                    al[i][2] = __float_as_uint(q[4]);
                    al[i][3] = __float_as_uint(q[8 * TROW + 4]);
                }
            }
#pragma unroll
            for (int j = 0; j < 8; j++) {
                const float* p = Bh + (wn + j * 8 + ar) * TROW + kb;
                bh[j][0] = __float_as_uint(p[0]);
                bh[j][1] = __float_as_uint(p[4]);
                if (SPLIT) {
                    const float* q = Bl + (wn + j * 8 + ar) * TROW + kb;
                    bl[j][0] = __float_as_uint(q[0]);
                    bl[j][1] = __float_as_uint(q[4]);
                }
            }
#pragma unroll
            for (int i = 0; i < 2; i++)
#pragma unroll
                for (int j = 0; j < 8; j++) {
                    MMA8(c[i][j], ah[i], bh[j]);
                    if (SPLIT) {
                        MMA8(c[i][j], ah[i], bl[j]);
                        MMA8(c[i][j], al[i], bh[j]);
                    }
                }
        }
        __syncthreads();
    }

    // epilogue
#pragma unroll
    for (int i = 0; i < 2; i++) {
        const int r0 = row0 + wm + i * 16 + ar;
#pragma unroll
        for (int j = 0; j < 8; j++) {
            const int cc = col0 + wn + j * 8 + ac * 2;
            float2 v0 = {c[i][j][0], c[i][j][1]};
            float2 v1 = {c[i][j][2], c[i][j][3]};
            if (bias) {
                float2 bb = *(const float2*)&bias[cc];
                v0.x += bb.x; v0.y += bb.y;
                v1.x += bb.x; v1.y += bb.y;
            }
            *(float2*)&C[(size_t)r0 * N + cc]       = v0;
            *(float2*)&C[(size_t)(r0 + 8) * N + cc] = v1;
        }
    }
}

// ---------------- V transpose: Vt[j][k] = V[k][j] ----------------------------
__global__ void __launch_bounds__(256)
transpose_kernel(const float* __restrict__ V, float* __restrict__ Vt)
{
    __shared__ float tile[32][33];
    int bx = blockIdx.x * 32;   // col in V (j, over TWOH)
    int by = blockIdx.y * 32;   // row in V (k, over NK)
    int tx = threadIdx.x & 31;
    int ty = threadIdx.x >> 5;  // 0..7
#pragma unroll
    for (int j = 0; j < 32; j += 8)
        tile[ty + j][tx] = V[(size_t)(by + ty + j) * TWOH_ + bx + tx];
    __syncthreads();
#pragma unroll
    for (int j = 0; j < 32; j += 8)
        Vt[(size_t)(bx + ty + j) * NK_ + by + tx] = tile[tx][ty + j];
}

// ---------------- softmax over axis 0 ---------------------------------------
__global__ void __launch_bounds__(256)
softmax_partial_kernel(const float* __restrict__ scores)
{
    int j  = blockIdx.x * 256 + threadIdx.x;
    int i0 = blockIdx.y * (NS_ / RSPLIT);
    float m = -INFINITY, s = 0.0f;
#pragma unroll 4
    for (int i = i0; i < i0 + NS_ / RSPLIT; i++) {
        float x = scores[(size_t)i * NK_ + j];
        if (x <= m) {
            s += __expf(x - m);
        } else {
            s = s * __expf(m - x) + 1.0f;
            m = x;
        }
    }
    g_pmax[blockIdx.y * NK_ + j] = m;
    g_psum[blockIdx.y * NK_ + j] = s;
}

__global__ void __launch_bounds__(256)
softmax_combine_kernel()
{
    int j = blockIdx.x * 256 + threadIdx.x;
    float m = -INFINITY, s = 0.0f;
#pragma unroll
    for (int r = 0; r < RSPLIT; r++) {
        float pm = g_pmax[r * NK_ + j];
        float ps = g_psum[r * NK_ + j];
        if (pm <= m) {
            s += ps * __expf(pm - m);
        } else {
            s = s * __expf(m - pm) + ps;
            m = pm;
        }
    }
    g_cmax[j] = m;
    g_cinv[j] = 1.0f / s;
}

__global__ void __launch_bounds__(256)
softmax_normalize_kernel(float* __restrict__ attn)
{
    size_t idx = (size_t)blockIdx.x * 256 + threadIdx.x;
    int j4 = (int)(idx % (NK_ / 4));
    float4 x  = ((float4*)attn)[idx];
    float4 mm = *(const float4*)&g_cmax[j4 * 4];
    float4 ii = *(const float4*)&g_cinv[j4 * 4];
    x.x = __expf(x.x - mm.x) * ii.x;
    x.y = __expf(x.y - mm.y) * ii.y;
    x.z = __expf(x.z - mm.z) * ii.z;
    x.w = __expf(x.w - mm.w) * ii.w;
    ((float4*)attn)[idx] = x;
}

// ---------------- launcher ---------------------------------------------------
extern "C" void kernel_launch(void* const* d_in, const int* in_sizes, int n_in,
                              void* d_out, int out_size)
{
    (void)in_sizes; (void)n_in; (void)out_size;
    const float* sent  = (const float*)d_in[0];   // [NS, SENT]
    const float* knowl = (const float*)d_in[1];   // [NK, 2H]
    const float* Ws    = (const float*)d_in[2];   // [HID, SENT]
    const float* bs    = (const float*)d_in[3];   // [HID]
    const float* Wk    = (const float*)d_in[4];   // [HID, 2H]
    const float* bk    = (const float*)d_in[5];   // [HID]

    float* attn  = (float*)d_out;                        // [NS, NK]
    float* fused = (float*)d_out + (size_t)NS_ * NK_;    // [NS, 2H]

    float *dS, *dK, *dVt;
    cudaGetSymbolAddress((void**)&dS,  g_S);
    cudaGetSymbolAddress((void**)&dK,  g_K);
    cudaGetSymbolAddress((void**)&dVt, g_Vt);

    cudaFuncSetAttribute(tgemm<true>,
                         cudaFuncAttributeMaxDynamicSharedMemorySize, SMEM_SPLIT);
    cudaFuncSetAttribute(tgemm<false>,
                         cudaFuncAttributeMaxDynamicSharedMemorySize, SMEM_SPLIT);

    dim3 blk(256);

    // Vt = V^T (rounding happens inline in the consuming GEMM's tile load)
    transpose_kernel<<<dim3(TWOH_ / 32, NK_ / 32), blk>>>(knowl, dVt);

    // S = sent @ Ws^T + bs   [NS, HID]   (3xTF32)
    tgemm<true><<<dim3(HID_ / 128, NS_ / 128), blk, SMEM_SPLIT>>>(
        sent, Ws, bs, dS, NS_, HID_, SENT_);
    // K = knowl @ Wk^T + bk  [NK, HID]   (3xTF32)
    tgemm<true><<<dim3(HID_ / 128, NK_ / 128), blk, SMEM_SPLIT>>>(
        knowl, Wk, bk, dK, NK_, HID_, TWOH_);
    // scores = S @ K^T       [NS, NK]    (3xTF32) -> attn region of d_out
    tgemm<true><<<dim3(NK_ / 128, NS_ / 128), blk, SMEM_SPLIT>>>(
        dS, dK, nullptr, attn, NS_, NK_, HID_);

    // softmax over axis 0 (columns)
    softmax_partial_kernel<<<dim3(NK_ / 256, RSPLIT), blk>>>(attn);
    softmax_combine_kernel<<<dim3(NK_ / 256), blk>>>();
    softmax_normalize_kernel<<<dim3((unsigned)((size_t)NS_ * NK_ / 4 / 256)), blk>>>(attn);

    // fused = attn @ V       [NS, 2H]    (single-pass tf32, rna operands)
    tgemm<false><<<dim3(TWOH_ / 128, NS_ / 128), blk, SMEM_PLAIN>>>(
        attn, dVt, nullptr, fused, NS_, TWOH_, NK_);
}